// round 4
// baseline (speedup 1.0000x reference)
#include <cuda_runtime.h>

// Shapes (fixed per reference setup_inputs)
#define L_DIM 4
#define B_DIM 8
#define C_DIM 256
#define HW 4096
#define QROW 1024                    // float4 per row
#define NROWS 8192                   // L*B*C
#define NBLOCKS 148
#define NT 256
#define REG_ROWS 6                   // rows held in registers (96 regs/thread)
#define SMEM_ROWS 13                 // rows held in shared (208 KB)
#define HELD (REG_ROWS + SMEM_ROWS)  // 19
#define BIG_BLOCKS 52                // 8192 = 52*56 + 96*55
#define MAX_CNT 56

// dynamic smem layout (float4 base):
//   [0, SMEM_ROWS*QROW)              row data        212,992 B
//   scratch: 56*8 floats             warp partials     1,792 B
//   gap_sh:  4*256 floats (phase 2)                    4,096 B
#define SMEM_BYTES (SMEM_ROWS * QROW * 16 + MAX_CNT * 8 * 4 + L_DIM * C_DIM * 4)

__device__ float g_gap[NROWS];
__device__ float g_attn[NROWS];
__device__ unsigned g_count;         // monotonic barrier counter (never reset)

extern __shared__ float4 sdyn[];

__device__ __forceinline__ float sum4(float4 v) { return (v.x + v.y) + (v.z + v.w); }

// warp-level partial for row j: 5 shfl + 1 STS, no block sync
__device__ __forceinline__ void warp_partial(float s, float* scratch, int j) {
    #pragma unroll
    for (int off = 16; off; off >>= 1) s += __shfl_xor_sync(0xffffffffu, s, off);
    if ((threadIdx.x & 31) == 0) scratch[j * 8 + (threadIdx.x >> 5)] = s;
}

// monotonic-counter grid barrier: works across unlimited graph replays
__device__ __forceinline__ void grid_sync() {
    __syncthreads();
    if (threadIdx.x == 0) {
        __threadfence();                               // release my gmem writes
        unsigned old = atomicAdd(&g_count, 1);
        unsigned goal = old - (old % NBLOCKS) + NBLOCKS;
        while ((int)(*(volatile unsigned*)&g_count - goal) < 0)
            __nanosleep(100);
        __threadfence();                               // acquire others' writes
    }
    __syncthreads();
}

__global__ __launch_bounds__(NT, 1) void sffm_persistent(
    const float4* __restrict__ in4,
    const float*  __restrict__ Wlin,
    float4*       __restrict__ out4)
{
    const int t = threadIdx.x;
    const int bid = blockIdx.x;
    int start, cnt;
    if (bid < BIG_BLOCKS) { start = bid * 56; cnt = 56; }
    else                  { start = BIG_BLOCKS * 56 + (bid - BIG_BLOCKS) * 55; cnt = 55; }

    float* scratch = (float*)(sdyn + SMEM_ROWS * QROW);
    float* gap_sh  = scratch + MAX_CNT * 8;

    // ================= Phase 1: GAP + stage held rows =================
    float4 rdat[REG_ROWS][4];

    // register-held rows: 24 independent LDG.128 front-loaded
    #pragma unroll
    for (int j = 0; j < REG_ROWS; j++) {
        const float4* p = in4 + (size_t)(start + j) * QROW;
        #pragma unroll
        for (int k = 0; k < 4; k++) rdat[j][k] = p[t + 256 * k];
    }
    #pragma unroll
    for (int j = 0; j < REG_ROWS; j++) {
        float s = sum4(rdat[j][0]) + sum4(rdat[j][1]) + sum4(rdat[j][2]) + sum4(rdat[j][3]);
        warp_partial(s, scratch, j);
    }

    // smem-held rows, pairs (8 loads in flight)
    #pragma unroll
    for (int j = 0; j < SMEM_ROWS - 1; j += 2) {
        const float4* p0 = in4 + (size_t)(start + REG_ROWS + j) * QROW;
        const float4* p1 = p0 + QROW;
        float4 a0 = p0[t], a1 = p0[t+256], a2 = p0[t+512], a3 = p0[t+768];
        float4 b0 = p1[t], b1 = p1[t+256], b2 = p1[t+512], b3 = p1[t+768];
        float4* s0 = sdyn + (size_t)j * QROW;
        float4* s1 = s0 + QROW;
        s0[t] = a0; s0[t+256] = a1; s0[t+512] = a2; s0[t+768] = a3;
        s1[t] = b0; s1[t+256] = b1; s1[t+512] = b2; s1[t+768] = b3;
        warp_partial(sum4(a0)+sum4(a1)+sum4(a2)+sum4(a3), scratch, REG_ROWS + j);
        warp_partial(sum4(b0)+sum4(b1)+sum4(b2)+sum4(b3), scratch, REG_ROWS + j + 1);
    }
    {   // odd last smem row (SMEM_ROWS = 13)
        const int j = SMEM_ROWS - 1;
        const float4* p = in4 + (size_t)(start + REG_ROWS + j) * QROW;
        float4 a0 = p[t], a1 = p[t+256], a2 = p[t+512], a3 = p[t+768];
        float4* s0 = sdyn + (size_t)j * QROW;
        s0[t] = a0; s0[t+256] = a1; s0[t+512] = a2; s0[t+768] = a3;
        warp_partial(sum4(a0)+sum4(a1)+sum4(a2)+sum4(a3), scratch, REG_ROWS + j);
    }

    // streamed rows, pairs (8 loads in flight); these populate L2 for phase 3
    int j = HELD;
    for (; j + 1 < cnt; j += 2) {
        const float4* p0 = in4 + (size_t)(start + j) * QROW;
        const float4* p1 = p0 + QROW;
        float4 a0 = p0[t], a1 = p0[t+256], a2 = p0[t+512], a3 = p0[t+768];
        float4 b0 = p1[t], b1 = p1[t+256], b2 = p1[t+512], b3 = p1[t+768];
        warp_partial(sum4(a0)+sum4(a1)+sum4(a2)+sum4(a3), scratch, j);
        warp_partial(sum4(b0)+sum4(b1)+sum4(b2)+sum4(b3), scratch, j + 1);
    }
    if (j < cnt) {
        const float4* p = in4 + (size_t)(start + j) * QROW;
        float4 a0 = p[t], a1 = p[t+256], a2 = p[t+512], a3 = p[t+768];
        warp_partial(sum4(a0)+sum4(a1)+sum4(a2)+sum4(a3), scratch, j);
    }

    __syncthreads();
    if (t < cnt) {                        // one thread finalizes one row
        float r = 0.f;
        #pragma unroll
        for (int k = 0; k < 8; k++) r += scratch[t * 8 + k];
        g_gap[start + t] = r * (1.0f / (float)HW);
    }

    grid_sync();

    // ================= Phase 2: scores + softmax (blocks 0..7) =================
    if (bid < B_DIM) {
        const int b = bid, d = t;
        for (int i = t; i < L_DIM * C_DIM; i += NT)
            gap_sh[i] = __ldcg(&g_gap[(i >> 8) * (B_DIM * C_DIM) + b * C_DIM + (i & 255)]);
        __syncthreads();

        float acc0 = 0.f, acc1 = 0.f, acc2 = 0.f, acc3 = 0.f;
        const float* wrow = Wlin + (size_t)d * C_DIM;
        #pragma unroll 8
        for (int c = 0; c < C_DIM; ++c) {
            float w = __ldg(&wrow[c]);
            acc0 = fmaf(gap_sh[0 * C_DIM + c], w, acc0);
            acc1 = fmaf(gap_sh[1 * C_DIM + c], w, acc1);
            acc2 = fmaf(gap_sh[2 * C_DIM + c], w, acc2);
            acc3 = fmaf(gap_sh[3 * C_DIM + c], w, acc3);
        }
        float m = fmaxf(fmaxf(acc0, acc1), fmaxf(acc2, acc3));
        float e0 = __expf(acc0 - m), e1 = __expf(acc1 - m);
        float e2 = __expf(acc2 - m), e3 = __expf(acc3 - m);
        float inv = 1.0f / (e0 + e1 + e2 + e3);
        const int base = b * C_DIM + d;
        g_attn[0 * (B_DIM * C_DIM) + base] = e0 * inv;
        g_attn[1 * (B_DIM * C_DIM) + base] = e1 * inv;
        g_attn[2 * (B_DIM * C_DIM) + base] = e2 * inv;
        g_attn[3 * (B_DIM * C_DIM) + base] = e3 * inv;
    }

    grid_sync();

    // ================= Phase 3: out = in * attn =================
    // streamed rows first, in REVERSE (freshest L2 lines first), pairs
    int jr = cnt - 1;
    for (; jr - 1 >= HELD; jr -= 2) {
        const int r0 = start + jr, r1 = start + jr - 1;
        float a0 = __ldcg(&g_attn[r0]);
        float a1 = __ldcg(&g_attn[r1]);
        const float4* p0 = in4 + (size_t)r0 * QROW;
        const float4* p1 = in4 + (size_t)r1 * QROW;
        float4* q0 = out4 + (size_t)r0 * QROW;
        float4* q1 = out4 + (size_t)r1 * QROW;
        float4 v0 = p0[t], v1 = p0[t+256], v2 = p0[t+512], v3 = p0[t+768];
        float4 w0 = p1[t], w1 = p1[t+256], w2 = p1[t+512], w3 = p1[t+768];
        v0.x*=a0; v0.y*=a0; v0.z*=a0; v0.w*=a0;
        v1.x*=a0; v1.y*=a0; v1.z*=a0; v1.w*=a0;
        v2.x*=a0; v2.y*=a0; v2.z*=a0; v2.w*=a0;
        v3.x*=a0; v3.y*=a0; v3.z*=a0; v3.w*=a0;
        w0.x*=a1; w0.y*=a1; w0.z*=a1; w0.w*=a1;
        w1.x*=a1; w1.y*=a1; w1.z*=a1; w1.w*=a1;
        w2.x*=a1; w2.y*=a1; w2.z*=a1; w2.w*=a1;
        w3.x*=a1; w3.y*=a1; w3.z*=a1; w3.w*=a1;
        __stcs(&q0[t], v0); __stcs(&q0[t+256], v1); __stcs(&q0[t+512], v2); __stcs(&q0[t+768], v3);
        __stcs(&q1[t], w0); __stcs(&q1[t+256], w1); __stcs(&q1[t+512], w2); __stcs(&q1[t+768], w3);
    }
    if (jr == HELD) {
        const int r0 = start + jr;
        float a = __ldcg(&g_attn[r0]);
        const float4* p = in4 + (size_t)r0 * QROW;
        float4* q = out4 + (size_t)r0 * QROW;
        float4 v0 = p[t], v1 = p[t+256], v2 = p[t+512], v3 = p[t+768];
        v0.x*=a; v0.y*=a; v0.z*=a; v0.w*=a;
        v1.x*=a; v1.y*=a; v1.z*=a; v1.w*=a;
        v2.x*=a; v2.y*=a; v2.z*=a; v2.w*=a;
        v3.x*=a; v3.y*=a; v3.z*=a; v3.w*=a;
        __stcs(&q[t], v0); __stcs(&q[t+256], v1); __stcs(&q[t+512], v2); __stcs(&q[t+768], v3);
    }

    // smem-held rows: no gmem read
    #pragma unroll
    for (int s = 0; s < SMEM_ROWS; s++) {
        const int row = start + REG_ROWS + s;
        float a = __ldcg(&g_attn[row]);
        float4* sp = sdyn + (size_t)s * QROW;
        float4* q  = out4 + (size_t)row * QROW;
        float4 v0 = sp[t], v1 = sp[t+256], v2 = sp[t+512], v3 = sp[t+768];
        v0.x*=a; v0.y*=a; v0.z*=a; v0.w*=a;
        v1.x*=a; v1.y*=a; v1.z*=a; v1.w*=a;
        v2.x*=a; v2.y*=a; v2.z*=a; v2.w*=a;
        v3.x*=a; v3.y*=a; v3.z*=a; v3.w*=a;
        __stcs(&q[t], v0); __stcs(&q[t+256], v1); __stcs(&q[t+512], v2); __stcs(&q[t+768], v3);
    }

    // register-held rows: no gmem read
    #pragma unroll
    for (int r = 0; r < REG_ROWS; r++) {
        const int row = start + r;
        float a = __ldcg(&g_attn[row]);
        float4* q = out4 + (size_t)row * QROW;
        #pragma unroll
        for (int k = 0; k < 4; k++) {
            float4 v = rdat[r][k];
            v.x *= a; v.y *= a; v.z *= a; v.w *= a;
            __stcs(&q[t + 256 * k], v);
        }
    }
}

// ---------------------------------------------------------------------------
extern "C" void kernel_launch(void* const* d_in, const int* in_sizes, int n_in,
                              void* d_out, int out_size) {
    const float4* in4  = (const float4*)d_in[0];
    const float*  Wlin = (const float*)d_in[1];
    float4*       out4 = (float4*)d_out;

    cudaFuncSetAttribute(sffm_persistent,
                         cudaFuncAttributeMaxDynamicSharedMemorySize, SMEM_BYTES);
    sffm_persistent<<<NBLOCKS, NT, SMEM_BYTES>>>(in4, Wlin, out4);
}

// round 6
// speedup vs baseline: 1.1753x; 1.1753x over previous
#include <cuda_runtime.h>

// Shapes (fixed per reference setup_inputs)
#define L_DIM 4
#define B_DIM 8
#define C_DIM 256
#define HW 4096                 // 64*64 spatial
#define NROWS (L_DIM * B_DIM * C_DIM)   // 8192
#define N_ELEM (NROWS * HW)             // 33,554,432

// Scratch (no allocations allowed)
__device__ float g_gap[NROWS];
__device__ float g_attn[NROWS];

// ---------------------------------------------------------------------------
// Kernel 1: GAP — one block per (l,b,c) row, reduce 4096 floats -> mean
// Default cache policy: these reads populate L2 for reuse by scale_kernel.
// 23.8us @ ~5.8 TB/s — near practical read ceiling.
// ---------------------------------------------------------------------------
__global__ __launch_bounds__(256) void gap_kernel(const float4* __restrict__ in4) {
    const int row = blockIdx.x;                       // 0..8191
    const float4* p = in4 + (size_t)row * (HW / 4);   // 1024 float4 per row

    // 4 independent loads front-loaded (MLP=4)
    float4 v0 = p[threadIdx.x];
    float4 v1 = p[threadIdx.x + 256];
    float4 v2 = p[threadIdx.x + 512];
    float4 v3 = p[threadIdx.x + 768];

    float s = ((v0.x + v0.y) + (v0.z + v0.w))
            + ((v1.x + v1.y) + (v1.z + v1.w))
            + ((v2.x + v2.y) + (v2.z + v2.w))
            + ((v3.x + v3.y) + (v3.z + v3.w));

    #pragma unroll
    for (int off = 16; off > 0; off >>= 1)
        s += __shfl_xor_sync(0xffffffffu, s, off);

    __shared__ float warp_sums[8];
    if ((threadIdx.x & 31) == 0) warp_sums[threadIdx.x >> 5] = s;
    __syncthreads();

    if (threadIdx.x < 8) {
        float t = warp_sums[threadIdx.x];
        #pragma unroll
        for (int off = 4; off > 0; off >>= 1)
            t += __shfl_xor_sync(0xffu, t, off);
        if (threadIdx.x == 0)
            g_gap[row] = t * (1.0f / (float)HW);
    }
}

// ---------------------------------------------------------------------------
// Kernel 2: scores = gap @ W^T, softmax over L per (b, d) -> g_attn[l,b,d]
// ---------------------------------------------------------------------------
__global__ __launch_bounds__(256) void attn_kernel(const float* __restrict__ Wlin) {
    const int b = blockIdx.x;
    const int d = threadIdx.x;

    __shared__ float gap_sh[L_DIM][C_DIM];
    #pragma unroll
    for (int l = 0; l < L_DIM; ++l)
        gap_sh[l][d] = g_gap[l * (B_DIM * C_DIM) + b * C_DIM + d];
    __syncthreads();

    float acc0 = 0.f, acc1 = 0.f, acc2 = 0.f, acc3 = 0.f;
    const float* wrow = Wlin + (size_t)d * C_DIM;   // W[d, :]
    #pragma unroll 8
    for (int c = 0; c < C_DIM; ++c) {
        float w = __ldg(&wrow[c]);
        acc0 = fmaf(gap_sh[0][c], w, acc0);
        acc1 = fmaf(gap_sh[1][c], w, acc1);
        acc2 = fmaf(gap_sh[2][c], w, acc2);
        acc3 = fmaf(gap_sh[3][c], w, acc3);
    }

    float m = fmaxf(fmaxf(acc0, acc1), fmaxf(acc2, acc3));
    float e0 = __expf(acc0 - m);
    float e1 = __expf(acc1 - m);
    float e2 = __expf(acc2 - m);
    float e3 = __expf(acc3 - m);
    float inv = 1.0f / (e0 + e1 + e2 + e3);

    const int base = b * C_DIM + d;
    g_attn[0 * (B_DIM * C_DIM) + base] = e0 * inv;
    g_attn[1 * (B_DIM * C_DIM) + base] = e1 * inv;
    g_attn[2 * (B_DIM * C_DIM) + base] = e2 * inv;
    g_attn[3 * (B_DIM * C_DIM) + base] = e3 * inv;
}

// ---------------------------------------------------------------------------
// Kernel 3: out = in * attn[row].
// - 2 rows per block, 8 independent front-loaded LDG.128 (MLP=8, enough to
//   cover L2-hit latency ~240cyc)
// - REVERSE traversal: freshest L2 lines from gap_kernel first
// - Loads: default policy (harvest L2 hits)
// - Stores: __stwt WRITE-THROUGH — do NOT allocate L2 lines, so the output
//   stream cannot evict the resident input. This is the key change.
// ---------------------------------------------------------------------------
__global__ __launch_bounds__(256) void scale_kernel(const float4* __restrict__ in4,
                                                    float4* __restrict__ out4) {
    const int r0 = (NROWS - 1) - 2 * blockIdx.x;      // reverse, 2 rows/block
    const int r1 = r0 - 1;
    const float a0 = g_attn[r0];
    const float a1 = g_attn[r1];
    const float4* p0 = in4 + (size_t)r0 * (HW / 4);
    const float4* p1 = in4 + (size_t)r1 * (HW / 4);
    float4* q0 = out4 + (size_t)r0 * (HW / 4);
    float4* q1 = out4 + (size_t)r1 * (HW / 4);
    const int t = threadIdx.x;

    // 8 independent loads front-loaded
    float4 v0 = p0[t];
    float4 v1 = p0[t + 256];
    float4 v2 = p0[t + 512];
    float4 v3 = p0[t + 768];
    float4 w0 = p1[t];
    float4 w1 = p1[t + 256];
    float4 w2 = p1[t + 512];
    float4 w3 = p1[t + 768];

    v0.x *= a0; v0.y *= a0; v0.z *= a0; v0.w *= a0;
    v1.x *= a0; v1.y *= a0; v1.z *= a0; v1.w *= a0;
    v2.x *= a0; v2.y *= a0; v2.z *= a0; v2.w *= a0;
    v3.x *= a0; v3.y *= a0; v3.z *= a0; v3.w *= a0;
    w0.x *= a1; w0.y *= a1; w0.z *= a1; w0.w *= a1;
    w1.x *= a1; w1.y *= a1; w1.z *= a1; w1.w *= a1;
    w2.x *= a1; w2.y *= a1; w2.z *= a1; w2.w *= a1;
    w3.x *= a1; w3.y *= a1; w3.z *= a1; w3.w *= a1;

    // write-through stores: no L2 allocation, input stays resident
    __stwt(&q0[t],       v0);
    __stwt(&q0[t + 256], v1);
    __stwt(&q0[t + 512], v2);
    __stwt(&q0[t + 768], v3);
    __stwt(&q1[t],       w0);
    __stwt(&q1[t + 256], w1);
    __stwt(&q1[t + 512], w2);
    __stwt(&q1[t + 768], w3);
}

// ---------------------------------------------------------------------------
extern "C" void kernel_launch(void* const* d_in, const int* in_sizes, int n_in,
                              void* d_out, int out_size) {
    const float4* in4  = (const float4*)d_in[0];
    const float*  Wlin = (const float*)d_in[1];
    float4*       out4 = (float4*)d_out;

    gap_kernel<<<NROWS, 256>>>(in4);
    attn_kernel<<<B_DIM, 256>>>(Wlin);
    scale_kernel<<<NROWS / 2, 256>>>(in4, out4);
}

// round 7
// speedup vs baseline: 1.8584x; 1.5812x over previous
#include <cuda_runtime.h>

// Shapes (fixed per reference setup_inputs)
#define L_DIM 4
#define B_DIM 8
#define C_DIM 256
#define HW 4096                 // 64*64 spatial
#define QROW (HW / 4)           // 1024 float4 per row
#define NROWS (L_DIM * B_DIM * C_DIM)   // 8192

// Scratch (no allocations allowed)
__device__ float g_gap[NROWS];

__device__ __forceinline__ float sum4(float4 v) { return (v.x + v.y) + (v.z + v.w); }

// ---------------------------------------------------------------------------
// Kernel 1: GAP — 2 rows per block, 8 independent front-loaded LDG.128
// ---------------------------------------------------------------------------
__global__ __launch_bounds__(256) void gap_kernel(const float4* __restrict__ in4) {
    const int r0 = 2 * blockIdx.x;
    const int r1 = r0 + 1;
    const float4* p0 = in4 + (size_t)r0 * QROW;
    const float4* p1 = in4 + (size_t)r1 * QROW;
    const int t = threadIdx.x;

    float4 a0 = p0[t], a1 = p0[t + 256], a2 = p0[t + 512], a3 = p0[t + 768];
    float4 b0 = p1[t], b1 = p1[t + 256], b2 = p1[t + 512], b3 = p1[t + 768];

    float sA = sum4(a0) + sum4(a1) + sum4(a2) + sum4(a3);
    float sB = sum4(b0) + sum4(b1) + sum4(b2) + sum4(b3);

    #pragma unroll
    for (int off = 16; off > 0; off >>= 1) {
        sA += __shfl_xor_sync(0xffffffffu, sA, off);
        sB += __shfl_xor_sync(0xffffffffu, sB, off);
    }

    __shared__ float wsum[2][8];
    if ((t & 31) == 0) {
        wsum[0][t >> 5] = sA;
        wsum[1][t >> 5] = sB;
    }
    __syncthreads();

    if (t < 2) {
        float r = 0.f;
        #pragma unroll
        for (int k = 0; k < 8; k++) r += wsum[t][k];
        g_gap[r0 + t] = r * (1.0f / (float)HW);
    }
}

// ---------------------------------------------------------------------------
// Kernel 2 (fused): per-block attn recompute + scale + store.
// - 2 rows per block, reverse traversal
// - 8 streaming LDG.128 issued FIRST (long-pole DRAM reads in flight while
//   the attn prologue computes from L2-broadcast gap/W lines)
// - default write-back stores (L2 coalesces + casts out full lines)
// ---------------------------------------------------------------------------
__global__ __launch_bounds__(256) void scale_kernel(const float4* __restrict__ in4,
                                                    const float*  __restrict__ Wlin,
                                                    float4* __restrict__ out4) {
    const int r0 = (NROWS - 1) - 2 * blockIdx.x;      // reverse, 2 rows/block
    const int r1 = r0 - 1;
    const float4* p0 = in4 + (size_t)r0 * QROW;
    const float4* p1 = in4 + (size_t)r1 * QROW;
    float4* q0 = out4 + (size_t)r0 * QROW;
    float4* q1 = out4 + (size_t)r1 * QROW;
    const int t = threadIdx.x;

    // ---- issue the 8 big streaming loads first ----
    float4 v0 = p0[t];
    float4 v1 = p0[t + 256];
    float4 v2 = p0[t + 512];
    float4 v3 = p0[t + 768];
    float4 w0 = p1[t];
    float4 w1 = p1[t + 256];
    float4 w2 = p1[t + 512];
    float4 w3 = p1[t + 768];

    // ---- attn prologue (overlaps with loads in flight) ----
    // row = l*2048 + b*256 + d
    const int l0 = r0 >> 11, b0 = (r0 >> 8) & 7, d0 = r0 & 255;
    const int l1 = r1 >> 11, b1 = (r1 >> 8) & 7, d1 = r1 & 255;

    const float wtA = __ldg(&Wlin[d0 * C_DIM + t]);
    const float wtB = __ldg(&Wlin[d1 * C_DIM + t]);

    // 8 partial dot products: scores[l', b, d] contributions at c = t
    float s[8];
    #pragma unroll
    for (int l = 0; l < L_DIM; l++) {
        s[l]     = __ldg(&g_gap[l * (B_DIM * C_DIM) + b0 * C_DIM + t]) * wtA;
        s[4 + l] = __ldg(&g_gap[l * (B_DIM * C_DIM) + b1 * C_DIM + t]) * wtB;
    }
    #pragma unroll
    for (int k = 0; k < 8; k++) {
        #pragma unroll
        for (int off = 16; off > 0; off >>= 1)
            s[k] += __shfl_xor_sync(0xffffffffu, s[k], off);
    }

    __shared__ float red[8][8];     // [score][warp]
    __shared__ float attn_bc[2];
    if ((t & 31) == 0) {
        #pragma unroll
        for (int k = 0; k < 8; k++) red[k][t >> 5] = s[k];
    }
    __syncthreads();
    if (t < 8) {
        float r = 0.f;
        #pragma unroll
        for (int k = 0; k < 8; k++) r += red[t][k];
        red[t][0] = r;              // reduced score t (A:0-3, B:4-7)
    }
    __syncthreads();
    if (t == 0) {
        float sc0 = red[0][0], sc1 = red[1][0], sc2 = red[2][0], sc3 = red[3][0];
        float m = fmaxf(fmaxf(sc0, sc1), fmaxf(sc2, sc3));
        float e0 = __expf(sc0 - m), e1 = __expf(sc1 - m);
        float e2 = __expf(sc2 - m), e3 = __expf(sc3 - m);
        float inv = 1.0f / (e0 + e1 + e2 + e3);
        float eA[4] = {e0, e1, e2, e3};
        attn_bc[0] = eA[l0] * inv;

        float t0 = red[4][0], t1 = red[5][0], t2 = red[6][0], t3 = red[7][0];
        float mB = fmaxf(fmaxf(t0, t1), fmaxf(t2, t3));
        float f0 = __expf(t0 - mB), f1 = __expf(t1 - mB);
        float f2 = __expf(t2 - mB), f3 = __expf(t3 - mB);
        float invB = 1.0f / (f0 + f1 + f2 + f3);
        float eB[4] = {f0, f1, f2, f3};
        attn_bc[1] = eB[l1] * invB;
    }
    __syncthreads();
    const float a0 = attn_bc[0];
    const float a1 = attn_bc[1];

    // ---- multiply + store (default write-back) ----
    v0.x *= a0; v0.y *= a0; v0.z *= a0; v0.w *= a0;
    v1.x *= a0; v1.y *= a0; v1.z *= a0; v1.w *= a0;
    v2.x *= a0; v2.y *= a0; v2.z *= a0; v2.w *= a0;
    v3.x *= a0; v3.y *= a0; v3.z *= a0; v3.w *= a0;
    w0.x *= a1; w0.y *= a1; w0.z *= a1; w0.w *= a1;
    w1.x *= a1; w1.y *= a1; w1.z *= a1; w1.w *= a1;
    w2.x *= a1; w2.y *= a1; w2.z *= a1; w2.w *= a1;
    w3.x *= a1; w3.y *= a1; w3.z *= a1; w3.w *= a1;

    q0[t]       = v0;
    q0[t + 256] = v1;
    q0[t + 512] = v2;
    q0[t + 768] = v3;
    q1[t]       = w0;
    q1[t + 256] = w1;
    q1[t + 512] = w2;
    q1[t + 768] = w3;
}

// ---------------------------------------------------------------------------
extern "C" void kernel_launch(void* const* d_in, const int* in_sizes, int n_in,
                              void* d_out, int out_size) {
    const float4* in4  = (const float4*)d_in[0];
    const float*  Wlin = (const float*)d_in[1];
    float4*       out4 = (float4*)d_out;

    gap_kernel<<<NROWS / 2, 256>>>(in4);
    scale_kernel<<<NROWS / 2, 256>>>(in4, Wlin, out4);
}